// round 5
// baseline (speedup 1.0000x reference)
#include <cuda_runtime.h>

#define DIMV 512
#define KMAX 8192
#define NMAX 32768

#define BM 128
#define BK 128
#define BD 32

// Scratch (device globals; no allocation allowed)
__device__ float  g_csq[KMAX];
__device__ float  g_xsq[NMAX];
__device__ int    g_idx[NMAX];
__device__ double g_part[NMAX / 8];

// ---------------------------------------------------------------------------
// Row sum-of-squares, XLA-GPU-style warp reduction:
// lane-strided sequential fp32 accumulation (mul then add, NO fma contraction),
// then shfl_down tree 16/8/4/2/1. One warp per row.
// ---------------------------------------------------------------------------
__global__ void xsq_kernel(const float* __restrict__ x, int rows) {
    int warp = (blockIdx.x * blockDim.x + threadIdx.x) >> 5;
    int lane = threadIdx.x & 31;
    if (warp >= rows) return;
    const float* r = x + (size_t)warp * DIMV;
    float acc = 0.f;
    #pragma unroll 4
    for (int j = lane; j < DIMV; j += 32) {
        float v = r[j];
        acc = __fadd_rn(acc, __fmul_rn(v, v));
    }
    #pragma unroll
    for (int off = 16; off > 0; off >>= 1)
        acc = __fadd_rn(acc, __shfl_down_sync(0xffffffffu, acc, off));
    if (lane == 0) g_xsq[warp] = acc;
}

__global__ void csq_kernel(const float* __restrict__ cb, int rows) {
    int warp = (blockIdx.x * blockDim.x + threadIdx.x) >> 5;
    int lane = threadIdx.x & 31;
    if (warp >= rows) return;
    const float* r = cb + (size_t)warp * DIMV;
    float acc = 0.f;
    #pragma unroll 4
    for (int j = lane; j < DIMV; j += 32) {
        float v = r[j];
        acc = __fadd_rn(acc, __fmul_rn(v, v));
    }
    #pragma unroll
    for (int off = 16; off > 0; off >>= 1)
        acc = __fadd_rn(acc, __shfl_down_sync(0xffffffffu, acc, off));
    if (lane == 0) g_csq[warp] = acc;
}

// ---------------------------------------------------------------------------
// Main argmin-GEMM: CTA owns 128 tokens, loops over all K codes in 128-tiles.
// Per thread: 8 tokens x 8 codes via fma.rn.f32x2 (token-paired accumulators).
// Codebook tile is staged DUPLICATED in smem so b-frags are (c,c) pairs.
// Distance replicates reference fp32 rounding:
//   t = fmaf(-2, dot, x_sq)   (== fp32(x_sq - 2*dot), single rounding)
//   v = fp32(t + c_sq)
// Argmin: strict '<' in ascending code order (matches jnp.argmin tie-break),
// cross-thread merge compares (val, idx) lexicographically.
// ---------------------------------------------------------------------------
__global__ __launch_bounds__(256, 2) void vq_argmin_kernel(
    const float* __restrict__ x, const float* __restrict__ cb, int K)
{
    __shared__ float xs[BD][BM];        // 16 KB, d-major token tile
    __shared__ float cs[BD][2 * BK];    // 32 KB, d-major duplicated code tile

    const int tid = threadIdx.x;
    const int ty  = tid >> 4;     // 0..15 token group (8 tokens each)
    const int tx  = tid & 15;     // 0..15 code group  (8 strided codes each)
    const int m0  = blockIdx.x * BM;

    float best[8];
    int   bidx[8];
    float xq[8];
    #pragma unroll
    for (int i = 0; i < 8; i++) {
        best[i] = 3.4e38f;
        bidx[i] = 0;
        xq[i]   = g_xsq[m0 + ty * 8 + i];
    }

    const int lrow  = tid >> 1;          // 0..127 staging row
    const int lcol0 = (tid & 1) * 16;    // 0 or 16

    for (int k0 = 0; k0 < K; k0 += BK) {
        unsigned long long acc[4][8];
        #pragma unroll
        for (int i = 0; i < 4; i++)
            #pragma unroll
            for (int j = 0; j < 8; j++) acc[i][j] = 0ULL;

        for (int d0 = 0; d0 < DIMV; d0 += BD) {
            __syncthreads();
            const float* xg = x  + (size_t)(m0 + lrow) * DIMV + d0 + lcol0;
            const float* cg = cb + (size_t)(k0 + lrow) * DIMV + d0 + lcol0;
            #pragma unroll
            for (int q = 0; q < 4; q++) {
                float4 vx = *(const float4*)(xg + q * 4);
                float4 vc = *(const float4*)(cg + q * 4);
                int c = lcol0 + q * 4;
                xs[c + 0][lrow] = vx.x;
                xs[c + 1][lrow] = vx.y;
                xs[c + 2][lrow] = vx.z;
                xs[c + 3][lrow] = vx.w;
                cs[c + 0][2 * lrow] = vc.x; cs[c + 0][2 * lrow + 1] = vc.x;
                cs[c + 1][2 * lrow] = vc.y; cs[c + 1][2 * lrow + 1] = vc.y;
                cs[c + 2][2 * lrow] = vc.z; cs[c + 2][2 * lrow + 1] = vc.z;
                cs[c + 3][2 * lrow] = vc.w; cs[c + 3][2 * lrow + 1] = vc.w;
            }
            __syncthreads();

            #pragma unroll
            for (int dd = 0; dd < BD; dd++) {
                unsigned long long a2[4], b2[8];
                #pragma unroll
                for (int i = 0; i < 4; i++)
                    a2[i] = *(const unsigned long long*)&xs[dd][ty * 8 + 2 * i];
                #pragma unroll
                for (int j = 0; j < 8; j++)
                    b2[j] = *(const unsigned long long*)&cs[dd][2 * (tx + 16 * j)];
                #pragma unroll
                for (int i = 0; i < 4; i++)
                    #pragma unroll
                    for (int j = 0; j < 8; j++)
                        asm("fma.rn.f32x2 %0, %1, %2, %0;"
                            : "+l"(acc[i][j]) : "l"(a2[i]), "l"(b2[j]));
            }
        }

        // finalize this code tile (ascending j => ascending code index)
        #pragma unroll
        for (int j = 0; j < 8; j++) {
            int code = k0 + tx + 16 * j;
            float cq = g_csq[code];
            #pragma unroll
            for (int i2 = 0; i2 < 4; i2++) {
                unsigned long long a = acc[i2][j];
                float dlo = __uint_as_float((unsigned)(a & 0xffffffffu));
                float dhi = __uint_as_float((unsigned)(a >> 32));
                int i = 2 * i2;
                float t0 = __fmaf_rn(-2.f, dlo, xq[i]);
                float v0 = __fadd_rn(t0, cq);
                if (v0 < best[i]) { best[i] = v0; bidx[i] = code; }
                float t1 = __fmaf_rn(-2.f, dhi, xq[i + 1]);
                float v1 = __fadd_rn(t1, cq);
                if (v1 < best[i + 1]) { best[i + 1] = v1; bidx[i + 1] = code; }
            }
        }
    }

    // cross-thread (tx) merge via smem overlay on cs (done with tiles)
    __syncthreads();
    float* redv = &cs[0][0];                 // [16][128]
    int*   redi = (int*)(&cs[0][0] + 2048);  // [16][128]
    #pragma unroll
    for (int i = 0; i < 8; i++) {
        int m = ty * 8 + i;
        redv[tx * 128 + m] = best[i];
        redi[tx * 128 + m] = bidx[i];
    }
    __syncthreads();
    if (tid < BM) {
        float bv = redv[tid];
        int   bi = redi[tid];
        #pragma unroll
        for (int t = 1; t < 16; t++) {
            float v  = redv[t * 128 + tid];
            int   ix = redi[t * 128 + tid];
            if (v < bv || (v == bv && ix < bi)) { bv = v; bi = ix; }
        }
        g_idx[m0 + tid] = bi;
    }
}

// ---------------------------------------------------------------------------
// Epilogue: gather codebook rows -> quantized output, per-block fp64 partial
// of sum((q - f)^2) in a fixed deterministic order, optional index output.
// One warp per token, 8 tokens per block.
// ---------------------------------------------------------------------------
__global__ void epilogue_kernel(const float* __restrict__ x,
                                const float* __restrict__ cb,
                                float* __restrict__ outq,
                                float* __restrict__ outi,
                                int write_extra)
{
    __shared__ double ssum[8];
    int w = threadIdx.x >> 5, lane = threadIdx.x & 31;
    int t = blockIdx.x * 8 + w;
    int ci = g_idx[t];
    const float4* cr = (const float4*)(cb + (size_t)ci * DIMV);
    const float4* xr = (const float4*)(x + (size_t)t * DIMV);
    float4* orow = (float4*)(outq + (size_t)t * DIMV);
    double acc = 0.0;
    #pragma unroll
    for (int q = 0; q < 4; q++) {
        int f = lane + 32 * q;
        float4 c4 = cr[f];
        float4 x4 = xr[f];
        orow[f] = c4;
        double d0 = (double)c4.x - (double)x4.x;
        double d1 = (double)c4.y - (double)x4.y;
        double d2 = (double)c4.z - (double)x4.z;
        double d3 = (double)c4.w - (double)x4.w;
        acc += d0 * d0 + d1 * d1 + d2 * d2 + d3 * d3;
    }
    #pragma unroll
    for (int off = 16; off > 0; off >>= 1)
        acc += __shfl_down_sync(0xffffffffu, acc, off);
    if (lane == 0) ssum[w] = acc;
    __syncthreads();
    if (threadIdx.x == 0) {
        double s = 0.0;
        #pragma unroll
        for (int i = 0; i < 8; i++) s += ssum[i];
        g_part[blockIdx.x] = s;
    }
    if (write_extra && lane == 0) outi[t] = (float)ci;
}

__global__ void loss_kernel(int nparts, float* __restrict__ outloss, long long denom) {
    __shared__ double s[256];
    double a = 0.0;
    for (int i = threadIdx.x; i < nparts; i += 256) a += g_part[i];  // fixed order
    s[threadIdx.x] = a;
    __syncthreads();
    for (int st = 128; st > 0; st >>= 1) {
        if (threadIdx.x < st) s[threadIdx.x] += s[threadIdx.x + st];
        __syncthreads();
    }
    if (threadIdx.x == 0) {
        double mse = s[0] / (double)denom;
        *outloss = (float)(1.25 * mse);  // codebook + 0.25*commitment (same mse)
    }
}

// ---------------------------------------------------------------------------
extern "C" void kernel_launch(void* const* d_in, const int* in_sizes, int n_in,
                              void* d_out, int out_size) {
    const float* x  = (const float*)d_in[0];
    const float* cb = (const float*)d_in[1];
    int n = in_sizes[0] / DIMV;   // 32768
    int K = in_sizes[1] / DIMV;   // 8192
    float* out = (float*)d_out;

    long long qsz = (long long)n * DIMV;
    int full = (out_size >= (int)(qsz + 1 + n)) ? 1 : 0;
    float* outloss = full ? (out + qsz) : 0;
    float* outi    = full ? (out + qsz + 1) : 0;

    csq_kernel<<<K / 8, 256>>>(cb, K);
    xsq_kernel<<<n / 8, 256>>>(x, n);
    vq_argmin_kernel<<<n / BM, 256>>>(x, cb, K);
    epilogue_kernel<<<n / 8, 256>>>(x, cb, out, outi, full);
    if (full) loss_kernel<<<1, 256>>>(n / 8, outloss, qsz);
}